// round 2
// baseline (speedup 1.0000x reference)
#include <cuda_runtime.h>

#define S   2048
#define DM  2048
#define H   32
#define G   8
#define DK  64
#define HD  (H*DK)   // 2048
#define GD  (G*DK)   // 512

// Scratch (no cudaMalloc allowed) — 40 MB total
__device__ float g_qh[(size_t)S*HD];
__device__ float g_kh[(size_t)S*GD];
__device__ float g_vh[(size_t)S*GD];
__device__ float g_outh[(size_t)S*HD];

// ---------------------------------------------------------------------------
// Generic tiled GEMM with bias: C[M,N] = A[M,K] @ W[K,N] + bias
// BM=BN=64, BK=16, 256 threads, 4x4 micro-tile per thread.
// ---------------------------------------------------------------------------
__global__ void gemm_bias_k(const float* __restrict__ A,
                            const float* __restrict__ W,
                            const float* __restrict__ bias,
                            float* __restrict__ C,
                            int M, int N, int K)
{
    __shared__ float As[16][65];   // [k][m], padded
    __shared__ float Ws[16][64];   // [k][n]
    const int tx = threadIdx.x, ty = threadIdx.y;
    const int t  = ty * 16 + tx;
    const int m0 = blockIdx.y * 64;
    const int n0 = blockIdx.x * 64;

    float acc[4][4] = {};

    for (int k0 = 0; k0 < K; k0 += 16) {
        #pragma unroll
        for (int i = 0; i < 4; i++) {
            int idx = t + i * 256;
            int kk = idx & 15, mm = idx >> 4;
            As[kk][mm] = A[(size_t)(m0 + mm) * K + k0 + kk];
        }
        #pragma unroll
        for (int i = 0; i < 4; i++) {
            int idx = t + i * 256;
            int nn = idx & 63, kk = idx >> 6;
            Ws[kk][nn] = W[(size_t)(k0 + kk) * N + n0 + nn];
        }
        __syncthreads();
        #pragma unroll
        for (int k = 0; k < 16; k++) {
            float ra[4], rb[4];
            #pragma unroll
            for (int i = 0; i < 4; i++) ra[i] = As[k][ty * 4 + i];
            #pragma unroll
            for (int j = 0; j < 4; j++) rb[j] = Ws[k][tx * 4 + j];
            #pragma unroll
            for (int i = 0; i < 4; i++)
                #pragma unroll
                for (int j = 0; j < 4; j++)
                    acc[i][j] = fmaf(ra[i], rb[j], acc[i][j]);
        }
        __syncthreads();
    }

    #pragma unroll
    for (int i = 0; i < 4; i++) {
        int r = m0 + ty * 4 + i;
        #pragma unroll
        for (int j = 0; j < 4; j++) {
            int c = n0 + tx * 4 + j;
            float b = bias ? bias[c] : 0.0f;
            C[(size_t)r * N + c] = acc[i][j] + b;
        }
    }
}

// ---------------------------------------------------------------------------
// Scores: attn_raw[h, i, j] = (Qh[i,:] . Kg[j,:]) / 8, masked.
// mask is read as 32-bit words (harness materializes bool as f32 or i32):
// nonzero bits == True.
// ---------------------------------------------------------------------------
__global__ void scores_k(const float* __restrict__ qh,
                         const float* __restrict__ kh,
                         const unsigned int* __restrict__ mask,
                         float* __restrict__ attn)
{
    __shared__ float Qs[16][65];   // [d][m]
    __shared__ float Ks[16][65];   // [d][n]
    const int tx = threadIdx.x, ty = threadIdx.y;
    const int t  = ty * 16 + tx;
    const int j0 = blockIdx.x * 64;
    const int i0 = blockIdx.y * 64;
    const int h  = blockIdx.z;
    const int g  = h >> 2;

    const float* Qp = qh + (size_t)h * DK;
    const float* Kp = kh + (size_t)g * DK;

    float acc[4][4] = {};

    for (int dk = 0; dk < DK; dk += 16) {
        #pragma unroll
        for (int i = 0; i < 4; i++) {
            int idx = t + i * 256;
            int d = idx & 15, mm = idx >> 4;
            Qs[d][mm] = Qp[(size_t)(i0 + mm) * HD + dk + d];
            Ks[d][mm] = Kp[(size_t)(j0 + mm) * GD + dk + d];
        }
        __syncthreads();
        #pragma unroll
        for (int d = 0; d < 16; d++) {
            float ra[4], rb[4];
            #pragma unroll
            for (int i = 0; i < 4; i++) ra[i] = Qs[d][ty * 4 + i];
            #pragma unroll
            for (int j = 0; j < 4; j++) rb[j] = Ks[d][tx * 4 + j];
            #pragma unroll
            for (int i = 0; i < 4; i++)
                #pragma unroll
                for (int j = 0; j < 4; j++)
                    acc[i][j] = fmaf(ra[i], rb[j], acc[i][j]);
        }
        __syncthreads();
    }

    float* ap = attn + (size_t)h * S * S;
    #pragma unroll
    for (int i = 0; i < 4; i++) {
        int r = i0 + ty * 4 + i;
        #pragma unroll
        for (int j = 0; j < 4; j++) {
            int c = j0 + tx * 4 + j;
            float v = acc[i][j] * 0.125f;            // 1/sqrt(64)
            if (mask[(size_t)r * S + c] == 0u) v = -1e9f;
            ap[(size_t)r * S + c] = v;
        }
    }
}

// ---------------------------------------------------------------------------
// Row softmax in place over attn rows (H*S rows of length S).
// One block (256 threads) per row; 8 elements per thread held in registers.
// ---------------------------------------------------------------------------
__global__ void softmax_k(float* __restrict__ attn)
{
    const size_t row = blockIdx.x;
    float* p = attn + row * (size_t)S;
    const int t = threadIdx.x;

    float vals[8];
    float m = -3.4e38f;
    #pragma unroll
    for (int i = 0; i < 8; i++) {
        vals[i] = p[t + i * 256];
        m = fmaxf(m, vals[i]);
    }

    __shared__ float red[256];
    red[t] = m;
    __syncthreads();
    for (int s2 = 128; s2 > 0; s2 >>= 1) {
        if (t < s2) red[t] = fmaxf(red[t], red[t + s2]);
        __syncthreads();
    }
    m = red[0];
    __syncthreads();

    float sum = 0.0f;
    #pragma unroll
    for (int i = 0; i < 8; i++) {
        vals[i] = expf(vals[i] - m);
        sum += vals[i];
    }
    red[t] = sum;
    __syncthreads();
    for (int s2 = 128; s2 > 0; s2 >>= 1) {
        if (t < s2) red[t] += red[t + s2];
        __syncthreads();
    }
    const float inv = 1.0f / red[0];

    #pragma unroll
    for (int i = 0; i < 8; i++)
        p[t + i * 256] = vals[i] * inv;
}

// ---------------------------------------------------------------------------
// PV: outh[i, h*64+d] = sum_j attn[h,i,j] * Vg[j,d]
// Per block: 64 rows x 64 cols (DK), K = S swept in chunks of 16.
// ---------------------------------------------------------------------------
__global__ void pv_k(const float* __restrict__ attn,
                     const float* __restrict__ vh,
                     float* __restrict__ outh)
{
    __shared__ float As[64][17];   // [m][k]
    __shared__ float Bs[16][64];   // [k][n]
    const int tx = threadIdx.x, ty = threadIdx.y;
    const int t  = ty * 16 + tx;
    const int i0 = blockIdx.x * 64;
    const int h  = blockIdx.y;
    const int g  = h >> 2;

    const float* Ap = attn + (size_t)h * S * S;
    const float* Bp = vh + (size_t)g * DK;

    float acc[4][4] = {};

    for (int k0 = 0; k0 < S; k0 += 16) {
        #pragma unroll
        for (int i = 0; i < 4; i++) {
            int idx = t + i * 256;
            int kk = idx & 15, mm = idx >> 4;
            As[mm][kk] = Ap[(size_t)(i0 + mm) * S + k0 + kk];
        }
        #pragma unroll
        for (int i = 0; i < 4; i++) {
            int idx = t + i * 256;
            int nn = idx & 63, kk = idx >> 6;
            Bs[kk][nn] = Bp[(size_t)(k0 + kk) * GD + nn];
        }
        __syncthreads();
        #pragma unroll
        for (int k = 0; k < 16; k++) {
            float ra[4], rb[4];
            #pragma unroll
            for (int i = 0; i < 4; i++) ra[i] = As[ty * 4 + i][k];
            #pragma unroll
            for (int j = 0; j < 4; j++) rb[j] = Bs[k][tx * 4 + j];
            #pragma unroll
            for (int i = 0; i < 4; i++)
                #pragma unroll
                for (int j = 0; j < 4; j++)
                    acc[i][j] = fmaf(ra[i], rb[j], acc[i][j]);
        }
        __syncthreads();
    }

    #pragma unroll
    for (int i = 0; i < 4; i++) {
        int r = i0 + ty * 4 + i;
        #pragma unroll
        for (int j = 0; j < 4; j++)
            outh[(size_t)r * HD + h * DK + tx * 4 + j] = acc[i][j];
    }
}

// ---------------------------------------------------------------------------
extern "C" void kernel_launch(void* const* d_in, const int* in_sizes, int n_in,
                              void* d_out, int out_size)
{
    const float*        q    = (const float*)d_in[0];
    const float*        k    = (const float*)d_in[1];
    const float*        v    = (const float*)d_in[2];
    const unsigned int* mask = (const unsigned int*)d_in[3];
    const float*        wq   = (const float*)d_in[4];
    const float*        bq   = (const float*)d_in[5];
    const float*        wk   = (const float*)d_in[6];
    const float*        bk   = (const float*)d_in[7];
    const float*        wv   = (const float*)d_in[8];
    const float*        bv   = (const float*)d_in[9];
    const float*        wo   = (const float*)d_in[10];
    const float*        bo   = (const float*)d_in[11];

    float* out  = (float*)d_out;
    float* attn = out + (size_t)S * DM;   // outputs: [out | attn]

    float *qh, *kh, *vh, *outh;
    cudaGetSymbolAddress((void**)&qh,   g_qh);
    cudaGetSymbolAddress((void**)&kh,   g_kh);
    cudaGetSymbolAddress((void**)&vh,   g_vh);
    cudaGetSymbolAddress((void**)&outh, g_outh);

    dim3 thr(16, 16);

    // Projections
    gemm_bias_k<<<dim3(HD / 64, S / 64), thr>>>(q, wq, bq, qh, S, HD, DM);
    gemm_bias_k<<<dim3(GD / 64, S / 64), thr>>>(k, wk, bk, kh, S, GD, DM);
    gemm_bias_k<<<dim3(GD / 64, S / 64), thr>>>(v, wv, bv, vh, S, GD, DM);

    // Scores (scaled + masked) written into the attn output region
    scores_k<<<dim3(S / 64, S / 64, H), thr>>>(qh, kh, mask, attn);

    // Row softmax in place
    softmax_k<<<H * S, 256>>>(attn);

    // attn @ V  -> per-head outputs in [s, h*64+d] layout
    pv_k<<<dim3(S / 64, H), thr>>>(attn, vh, outh);

    // Output projection
    gemm_bias_k<<<dim3(DM / 64, S / 64), thr>>>(outh, wo, bo, out, S, DM, HD);
}

// round 4
// speedup vs baseline: 1.1609x; 1.1609x over previous
#include <cuda_runtime.h>

#define S   2048
#define DM  2048
#define H   32
#define G   8
#define DK  64
#define HD  (H*DK)   // 2048
#define GD  (G*DK)   // 512

// Scratch (no cudaMalloc allowed) — 40 MB total
__device__ float g_qh[(size_t)S*HD];
__device__ float g_kh[(size_t)S*GD];
__device__ float g_vh[(size_t)S*GD];
__device__ float g_outh[(size_t)S*HD];

// ---------------------------------------------------------------------------
// GEMM + bias: C[M,N] = A[M,K] @ W[K,N] + bias
// 128x128 tile, BK=8, 256 threads, 8x8 micro-tile, float4 loads, reg prefetch.
// ---------------------------------------------------------------------------
__global__ __launch_bounds__(256, 2)
void gemm_bias_k(const float* __restrict__ A,
                 const float* __restrict__ W,
                 const float* __restrict__ bias,
                 float* __restrict__ C,
                 int M, int N, int K)
{
    __shared__ float As[8][132];   // [k][m], padded
    __shared__ float Bs[8][128];   // [k][n]

    const int tid = threadIdx.x;
    const int m0 = blockIdx.y * 128;
    const int n0 = blockIdx.x * 128;

    const int tr = (tid >> 4) * 8;   // row in tile (0..120)
    const int tc = (tid & 15) * 8;   // col in tile (0..120)

    const int la_m = tid >> 1;            // 0..127
    const int la_k = (tid & 1) * 4;       // 0 or 4
    const int lb_k = tid >> 5;            // 0..7
    const int lb_n = (tid & 31) * 4;      // 0..124

    const float* Ap = A + (size_t)(m0 + la_m) * K + la_k;
    const float* Bp = W + (size_t)lb_k * N + n0 + lb_n;

    float acc[8][8] = {};

    float4 pa = *(const float4*)Ap;
    float4 pb = *(const float4*)Bp;

    for (int k0 = 0; k0 < K; k0 += 8) {
        As[la_k + 0][la_m] = pa.x;
        As[la_k + 1][la_m] = pa.y;
        As[la_k + 2][la_m] = pa.z;
        As[la_k + 3][la_m] = pa.w;
        *(float4*)&Bs[lb_k][lb_n] = pb;
        __syncthreads();

        if (k0 + 8 < K) {
            pa = *(const float4*)(Ap + k0 + 8);
            pb = *(const float4*)(Bp + (size_t)(k0 + 8) * N);
        }

        #pragma unroll
        for (int k = 0; k < 8; k++) {
            float4 a0 = *(const float4*)&As[k][tr];
            float4 a1 = *(const float4*)&As[k][tr + 4];
            float4 b0 = *(const float4*)&Bs[k][tc];
            float4 b1 = *(const float4*)&Bs[k][tc + 4];
            float ra[8] = {a0.x,a0.y,a0.z,a0.w,a1.x,a1.y,a1.z,a1.w};
            float rb[8] = {b0.x,b0.y,b0.z,b0.w,b1.x,b1.y,b1.z,b1.w};
            #pragma unroll
            for (int i = 0; i < 8; i++)
                #pragma unroll
                for (int j = 0; j < 8; j++)
                    acc[i][j] = fmaf(ra[i], rb[j], acc[i][j]);
        }
        __syncthreads();
    }

    float4 bias0 = *(const float4*)(bias + n0 + tc);
    float4 bias1 = *(const float4*)(bias + n0 + tc + 4);
    #pragma unroll
    for (int i = 0; i < 8; i++) {
        const int r = m0 + tr + i;
        float4 o0 = {acc[i][0]+bias0.x, acc[i][1]+bias0.y, acc[i][2]+bias0.z, acc[i][3]+bias0.w};
        float4 o1 = {acc[i][4]+bias1.x, acc[i][5]+bias1.y, acc[i][6]+bias1.z, acc[i][7]+bias1.w};
        *(float4*)&C[(size_t)r * N + n0 + tc]     = o0;
        *(float4*)&C[(size_t)r * N + n0 + tc + 4] = o1;
    }
}

// ---------------------------------------------------------------------------
// Scores: attn[h,i,j] = (Qh[i,:].Kg[j,:]) / 8, masked. 128x128 tile per block.
// ---------------------------------------------------------------------------
__global__ __launch_bounds__(256, 2)
void scores_k(const float* __restrict__ qh,
              const float* __restrict__ kh,
              const unsigned int* __restrict__ mask,
              float* __restrict__ attn)
{
    __shared__ float As[8][132];   // [d][i]
    __shared__ float Bs[8][132];   // [d][j]

    const int tid = threadIdx.x;
    const int j0 = blockIdx.x * 128;
    const int i0 = blockIdx.y * 128;
    const int h  = blockIdx.z;
    const int g  = h >> 2;

    const int tr = (tid >> 4) * 8;
    const int tc = (tid & 15) * 8;

    const int l_s = tid >> 1;         // 0..127
    const int l_d = (tid & 1) * 4;    // 0 or 4

    const float* Qp = qh + (size_t)(i0 + l_s) * HD + h * DK + l_d;
    const float* Kp = kh + (size_t)(j0 + l_s) * GD + g * DK + l_d;

    float acc[8][8] = {};

    float4 pa = *(const float4*)Qp;
    float4 pb = *(const float4*)Kp;

    for (int d0 = 0; d0 < DK; d0 += 8) {
        As[l_d + 0][l_s] = pa.x;
        As[l_d + 1][l_s] = pa.y;
        As[l_d + 2][l_s] = pa.z;
        As[l_d + 3][l_s] = pa.w;
        Bs[l_d + 0][l_s] = pb.x;
        Bs[l_d + 1][l_s] = pb.y;
        Bs[l_d + 2][l_s] = pb.z;
        Bs[l_d + 3][l_s] = pb.w;
        __syncthreads();

        if (d0 + 8 < DK) {
            pa = *(const float4*)(Qp + d0 + 8);
            pb = *(const float4*)(Kp + d0 + 8);
        }

        #pragma unroll
        for (int k = 0; k < 8; k++) {
            float4 a0 = *(const float4*)&As[k][tr];
            float4 a1 = *(const float4*)&As[k][tr + 4];
            float4 b0 = *(const float4*)&Bs[k][tc];
            float4 b1 = *(const float4*)&Bs[k][tc + 4];
            float ra[8] = {a0.x,a0.y,a0.z,a0.w,a1.x,a1.y,a1.z,a1.w};
            float rb[8] = {b0.x,b0.y,b0.z,b0.w,b1.x,b1.y,b1.z,b1.w};
            #pragma unroll
            for (int i = 0; i < 8; i++)
                #pragma unroll
                for (int j = 0; j < 8; j++)
                    acc[i][j] = fmaf(ra[i], rb[j], acc[i][j]);
        }
        __syncthreads();
    }

    float* ap = attn + (size_t)h * S * S;
    #pragma unroll
    for (int i = 0; i < 8; i++) {
        const size_t r = (size_t)(i0 + tr + i);
        uint4 m0v = *(const uint4*)(mask + r * S + j0 + tc);
        uint4 m1v = *(const uint4*)(mask + r * S + j0 + tc + 4);
        float4 o0, o1;
        o0.x = m0v.x ? acc[i][0]*0.125f : -1e9f;
        o0.y = m0v.y ? acc[i][1]*0.125f : -1e9f;
        o0.z = m0v.z ? acc[i][2]*0.125f : -1e9f;
        o0.w = m0v.w ? acc[i][3]*0.125f : -1e9f;
        o1.x = m1v.x ? acc[i][4]*0.125f : -1e9f;
        o1.y = m1v.y ? acc[i][5]*0.125f : -1e9f;
        o1.z = m1v.z ? acc[i][6]*0.125f : -1e9f;
        o1.w = m1v.w ? acc[i][7]*0.125f : -1e9f;
        *(float4*)&ap[r * S + j0 + tc]     = o0;
        *(float4*)&ap[r * S + j0 + tc + 4] = o1;
    }
}

// ---------------------------------------------------------------------------
// Row softmax in place, vectorized. One block (256 threads) per row of S=2048.
// ---------------------------------------------------------------------------
__device__ __forceinline__ float warp_max(float v) {
    #pragma unroll
    for (int o = 16; o > 0; o >>= 1) v = fmaxf(v, __shfl_xor_sync(0xffffffffu, v, o));
    return v;
}
__device__ __forceinline__ float warp_sum(float v) {
    #pragma unroll
    for (int o = 16; o > 0; o >>= 1) v += __shfl_xor_sync(0xffffffffu, v, o);
    return v;
}

__global__ __launch_bounds__(256)
void softmax_k(float* __restrict__ attn)
{
    const size_t row = blockIdx.x;
    float4* p = (float4*)(attn + row * (size_t)S);
    const int t = threadIdx.x;
    const int warp = t >> 5, lane = t & 31;
    __shared__ float red[8];

    float4 v0 = p[t];
    float4 v1 = p[t + 256];

    float m = fmaxf(fmaxf(fmaxf(v0.x, v0.y), fmaxf(v0.z, v0.w)),
                    fmaxf(fmaxf(v1.x, v1.y), fmaxf(v1.z, v1.w)));
    m = warp_max(m);
    if (lane == 0) red[warp] = m;
    __syncthreads();
    m = red[lane & 7];          // duplicates fine for max
    m = warp_max(m);

    v0.x = expf(v0.x - m); v0.y = expf(v0.y - m);
    v0.z = expf(v0.z - m); v0.w = expf(v0.w - m);
    v1.x = expf(v1.x - m); v1.y = expf(v1.y - m);
    v1.z = expf(v1.z - m); v1.w = expf(v1.w - m);

    float s = v0.x + v0.y + v0.z + v0.w + v1.x + v1.y + v1.z + v1.w;
    s = warp_sum(s);
    __syncthreads();
    if (lane == 0) red[warp] = s;
    __syncthreads();
    s = (lane < 8) ? red[lane] : 0.0f;   // FIX: each partial counted once
    s = warp_sum(s);
    const float inv = 1.0f / s;

    v0.x *= inv; v0.y *= inv; v0.z *= inv; v0.w *= inv;
    v1.x *= inv; v1.y *= inv; v1.z *= inv; v1.w *= inv;
    p[t] = v0;
    p[t + 256] = v1;
}

// ---------------------------------------------------------------------------
// PV: outh[i, h*64+d] = sum_j attn[h,i,j] * Vg[j,d]
// 128x64 tile, BK=16, 256 threads, 8x4 micro-tile.
// ---------------------------------------------------------------------------
__global__ __launch_bounds__(256, 2)
void pv_k(const float* __restrict__ attn,
          const float* __restrict__ vh,
          float* __restrict__ outh)
{
    __shared__ float As[16][132];  // [k][m]
    __shared__ float Bs[16][64];   // [k][n]

    const int tid = threadIdx.x;
    const int i0 = blockIdx.x * 128;
    const int h  = blockIdx.y;
    const int g  = h >> 2;

    const int tr = (tid >> 4) * 8;       // 0..120
    const int tc = (tid & 15) * 4;       // 0..60

    const int la_m = tid >> 2;           // 0..63
    const int la_k = (tid & 3) * 4;      // 0..12
    const int lb_k = tid >> 4;           // 0..15
    const int lb_n = (tid & 15) * 4;     // 0..60

    const float* Ap = attn + (size_t)h * S * S + (size_t)(i0 + la_m) * S + la_k;
    const float* Bp = vh + (size_t)lb_k * GD + g * DK + lb_n;

    float acc[8][4] = {};

    float4 pa0 = *(const float4*)Ap;
    float4 pa1 = *(const float4*)(Ap + (size_t)64 * S);
    float4 pb  = *(const float4*)Bp;

    for (int k0 = 0; k0 < S; k0 += 16) {
        As[la_k + 0][la_m] = pa0.x;
        As[la_k + 1][la_m] = pa0.y;
        As[la_k + 2][la_m] = pa0.z;
        As[la_k + 3][la_m] = pa0.w;
        As[la_k + 0][la_m + 64] = pa1.x;
        As[la_k + 1][la_m + 64] = pa1.y;
        As[la_k + 2][la_m + 64] = pa1.z;
        As[la_k + 3][la_m + 64] = pa1.w;
        *(float4*)&Bs[lb_k][lb_n] = pb;
        __syncthreads();

        if (k0 + 16 < S) {
            pa0 = *(const float4*)(Ap + k0 + 16);
            pa1 = *(const float4*)(Ap + (size_t)64 * S + k0 + 16);
            pb  = *(const float4*)(Bp + (size_t)(k0 + 16) * GD);
        }

        #pragma unroll
        for (int k = 0; k < 16; k++) {
            float4 a0 = *(const float4*)&As[k][tr];
            float4 a1 = *(const float4*)&As[k][tr + 4];
            float4 b0 = *(const float4*)&Bs[k][tc];
            float ra[8] = {a0.x,a0.y,a0.z,a0.w,a1.x,a1.y,a1.z,a1.w};
            float rb[4] = {b0.x,b0.y,b0.z,b0.w};
            #pragma unroll
            for (int i = 0; i < 8; i++)
                #pragma unroll
                for (int j = 0; j < 4; j++)
                    acc[i][j] = fmaf(ra[i], rb[j], acc[i][j]);
        }
        __syncthreads();
    }

    #pragma unroll
    for (int i = 0; i < 8; i++) {
        const int r = i0 + tr + i;
        float4 o = {acc[i][0], acc[i][1], acc[i][2], acc[i][3]};
        *(float4*)&outh[(size_t)r * HD + h * DK + tc] = o;
    }
}

// ---------------------------------------------------------------------------
extern "C" void kernel_launch(void* const* d_in, const int* in_sizes, int n_in,
                              void* d_out, int out_size)
{
    const float*        q    = (const float*)d_in[0];
    const float*        k    = (const float*)d_in[1];
    const float*        v    = (const float*)d_in[2];
    const unsigned int* mask = (const unsigned int*)d_in[3];
    const float*        wq   = (const float*)d_in[4];
    const float*        bq   = (const float*)d_in[5];
    const float*        wk   = (const float*)d_in[6];
    const float*        bk   = (const float*)d_in[7];
    const float*        wv   = (const float*)d_in[8];
    const float*        bv   = (const float*)d_in[9];
    const float*        wo   = (const float*)d_in[10];
    const float*        bo   = (const float*)d_in[11];

    float* out  = (float*)d_out;
    float* attn = out + (size_t)S * DM;   // outputs: [out | attn]

    float *qh, *kh, *vh, *outh;
    cudaGetSymbolAddress((void**)&qh,   g_qh);
    cudaGetSymbolAddress((void**)&kh,   g_kh);
    cudaGetSymbolAddress((void**)&vh,   g_vh);
    cudaGetSymbolAddress((void**)&outh, g_outh);

    // Projections
    gemm_bias_k<<<dim3(HD / 128, S / 128), 256>>>(q, wq, bq, qh, S, HD, DM);
    gemm_bias_k<<<dim3(GD / 128, S / 128), 256>>>(k, wk, bk, kh, S, GD, DM);
    gemm_bias_k<<<dim3(GD / 128, S / 128), 256>>>(v, wv, bv, vh, S, GD, DM);

    // Scores (scaled + masked) into attn output region
    scores_k<<<dim3(S / 128, S / 128, H), 256>>>(qh, kh, mask, attn);

    // Row softmax in place
    softmax_k<<<H * S, 256>>>(attn);

    // attn @ V
    pv_k<<<dim3(S / 128, H), 256>>>(attn, vh, outh);

    // Output projection
    gemm_bias_k<<<dim3(DM / 128, S / 128), 256>>>(outh, wo, bo, out, S, DM, HD);
}

// round 5
// speedup vs baseline: 1.6283x; 1.4026x over previous
#include <cuda_runtime.h>
#include <cuda_bf16.h>
#include <mma.h>

using namespace nvcuda;

#define S   2048
#define DM  2048
#define H   32
#define G   8
#define DK  64
#define HD  (H*DK)   // 2048
#define GD  (G*DK)   // 512

// Scratch (no cudaMalloc allowed)
__device__ float g_qh[(size_t)S*HD];
__device__ float g_kh[(size_t)S*GD];
__device__ float g_vh[(size_t)S*GD];
__device__ float g_outh[(size_t)S*HD];

using FragA  = wmma::fragment<wmma::matrix_a, 16,16,16, __nv_bfloat16, wmma::row_major>;
using FragBr = wmma::fragment<wmma::matrix_b, 16,16,16, __nv_bfloat16, wmma::row_major>;
using FragBc = wmma::fragment<wmma::matrix_b, 16,16,16, __nv_bfloat16, wmma::col_major>;
using FragC  = wmma::fragment<wmma::accumulator, 16,16,16, float>;

__device__ __forceinline__ void split2(float x, __nv_bfloat16& h, __nv_bfloat16& l) {
    h = __float2bfloat16_rn(x);
    l = __float2bfloat16_rn(x - __bfloat162float(h));
}
__device__ __forceinline__ void store_split4(float4 v, __nv_bfloat16* h, __nv_bfloat16* l) {
    split2(v.x, h[0], l[0]); split2(v.y, h[1], l[1]);
    split2(v.z, h[2], l[2]); split2(v.w, h[3], l[3]);
}

// ---------------------------------------------------------------------------
// GEMM + bias: C[M,N] = A[M,K] @ W[K,N] + bias.  bf16-split tensor cores.
// 128x128 tile, BK=32, 256 threads (8 warps), warp tile 32x64.
// ---------------------------------------------------------------------------
__global__ __launch_bounds__(256)
void gemm_bias_k(const float* __restrict__ A,
                 const float* __restrict__ W,
                 const float* __restrict__ bias,
                 float* __restrict__ C,
                 int M, int N, int K)
{
    __shared__ __align__(16) __nv_bfloat16 As_hi[128][40];
    __shared__ __align__(16) __nv_bfloat16 As_lo[128][40];
    __shared__ __align__(16) __nv_bfloat16 Bs_hi[32][136];
    __shared__ __align__(16) __nv_bfloat16 Bs_lo[32][136];
    __shared__ __align__(16) float biasTile[16][136];

    const int tid  = threadIdx.x;
    const int warp = tid >> 5;
    const int m0 = blockIdx.y * 128;
    const int n0 = blockIdx.x * 128;
    const int wm = warp >> 1;          // 0..3
    const int wn = warp & 1;           // 0..1
    const int m_base = wm * 32;
    const int n_base = wn * 64;

    // global load assignments
    const int la_m  = tid >> 1;            // 0..127
    const int la_k4 = (tid & 1) * 16;      // 0 or 16
    const int lb_k  = tid >> 3;            // 0..31
    const int lb_n  = (tid & 7) * 16;      // 0..112

    const float* Ap = A + (size_t)(m0 + la_m) * K + la_k4;
    const float* Bp = W + (size_t)lb_k * N + n0 + lb_n;

    // bias broadcast tile
    for (int idx = tid; idx < 16 * 128; idx += 256) {
        int r = idx >> 7, c = idx & 127;
        biasTile[r][c] = bias[n0 + c];
    }
    __syncthreads();

    FragC acc[2][4];
    #pragma unroll
    for (int i = 0; i < 2; i++)
        #pragma unroll
        for (int j = 0; j < 4; j++)
            wmma::load_matrix_sync(acc[i][j], &biasTile[0][n_base + j*16], 136, wmma::mem_row_major);

    float4 pa[4], pb[4];
    #pragma unroll
    for (int q = 0; q < 4; q++) {
        pa[q] = *(const float4*)(Ap + 4*q);
        pb[q] = *(const float4*)(Bp + 4*q);
    }

    for (int k0 = 0; k0 < K; k0 += 32) {
        #pragma unroll
        for (int q = 0; q < 4; q++) {
            store_split4(pa[q], &As_hi[la_m][la_k4 + 4*q], &As_lo[la_m][la_k4 + 4*q]);
            store_split4(pb[q], &Bs_hi[lb_k][lb_n + 4*q], &Bs_lo[lb_k][lb_n + 4*q]);
        }
        __syncthreads();

        if (k0 + 32 < K) {
            #pragma unroll
            for (int q = 0; q < 4; q++) {
                pa[q] = *(const float4*)(Ap + k0 + 32 + 4*q);
                pb[q] = *(const float4*)(Bp + (size_t)(k0 + 32) * N + 4*q);
            }
        }

        #pragma unroll
        for (int kf = 0; kf < 2; kf++) {
            FragA a_hi[2], a_lo[2];
            #pragma unroll
            for (int i = 0; i < 2; i++) {
                wmma::load_matrix_sync(a_hi[i], &As_hi[m_base + i*16][kf*16], 40);
                wmma::load_matrix_sync(a_lo[i], &As_lo[m_base + i*16][kf*16], 40);
            }
            #pragma unroll
            for (int j = 0; j < 4; j++) {
                FragBr b_hi, b_lo;
                wmma::load_matrix_sync(b_hi, &Bs_hi[kf*16][n_base + j*16], 136);
                wmma::load_matrix_sync(b_lo, &Bs_lo[kf*16][n_base + j*16], 136);
                #pragma unroll
                for (int i = 0; i < 2; i++) {
                    wmma::mma_sync(acc[i][j], a_hi[i], b_hi, acc[i][j]);
                    wmma::mma_sync(acc[i][j], a_hi[i], b_lo, acc[i][j]);
                    wmma::mma_sync(acc[i][j], a_lo[i], b_hi, acc[i][j]);
                }
            }
        }
        __syncthreads();
    }

    #pragma unroll
    for (int i = 0; i < 2; i++)
        #pragma unroll
        for (int j = 0; j < 4; j++)
            wmma::store_matrix_sync(C + (size_t)(m0 + m_base + i*16) * N + n0 + n_base + j*16,
                                    acc[i][j], N, wmma::mem_row_major);
}

// ---------------------------------------------------------------------------
// Scores: attn[h,i,j] = (Qh[i,:].Kg[j,:]) / 8, masked. 128x128 per block.
// Whole DK=64 staged in smem once; K^T via col_major B fragments.
// Dynamic smem; epilogue staged through reused smem.
// ---------------------------------------------------------------------------
__global__ __launch_bounds__(256)
void scores_k(const float* __restrict__ qh,
              const float* __restrict__ kh,
              const unsigned int* __restrict__ mask,
              float* __restrict__ attn)
{
    extern __shared__ char dyns[];
    __nv_bfloat16* Qh_s = (__nv_bfloat16*)dyns;        // [128][72]
    __nv_bfloat16* Ql_s = Qh_s + 128*72;
    __nv_bfloat16* Kh_s = Ql_s + 128*72;
    __nv_bfloat16* Kl_s = Kh_s + 128*72;
    float* stage = (float*)dyns;                       // [128][132] reuse

    const int tid  = threadIdx.x;
    const int warp = tid >> 5;
    const int j0 = blockIdx.x * 128;
    const int i0 = blockIdx.y * 128;
    const int h  = blockIdx.z;
    const int g  = h >> 2;
    const int wm = warp >> 1;
    const int wn = warp & 1;
    const int m_base = wm * 32;
    const int n_base = wn * 64;

    const int l_s = tid >> 1;          // 0..127
    const int l_d = (tid & 1) * 32;    // 0 or 32

    const float* Qp = qh + (size_t)(i0 + l_s) * HD + h * DK + l_d;
    const float* Kp = kh + (size_t)(j0 + l_s) * GD + g * DK + l_d;

    #pragma unroll
    for (int q = 0; q < 8; q++) {
        float4 vq = *(const float4*)(Qp + 4*q);
        vq.x *= 0.125f; vq.y *= 0.125f; vq.z *= 0.125f; vq.w *= 0.125f;
        store_split4(vq, &Qh_s[l_s*72 + l_d + 4*q], &Ql_s[l_s*72 + l_d + 4*q]);
        float4 vk = *(const float4*)(Kp + 4*q);
        store_split4(vk, &Kh_s[l_s*72 + l_d + 4*q], &Kl_s[l_s*72 + l_d + 4*q]);
    }
    __syncthreads();

    FragC acc[2][4];
    #pragma unroll
    for (int i = 0; i < 2; i++)
        #pragma unroll
        for (int j = 0; j < 4; j++)
            wmma::fill_fragment(acc[i][j], 0.0f);

    #pragma unroll
    for (int kf = 0; kf < 4; kf++) {
        FragA a_hi[2], a_lo[2];
        #pragma unroll
        for (int i = 0; i < 2; i++) {
            wmma::load_matrix_sync(a_hi[i], &Qh_s[(m_base + i*16)*72 + kf*16], 72);
            wmma::load_matrix_sync(a_lo[i], &Ql_s[(m_base + i*16)*72 + kf*16], 72);
        }
        #pragma unroll
        for (int j = 0; j < 4; j++) {
            FragBc b_hi, b_lo;
            wmma::load_matrix_sync(b_hi, &Kh_s[(n_base + j*16)*72 + kf*16], 72);
            wmma::load_matrix_sync(b_lo, &Kl_s[(n_base + j*16)*72 + kf*16], 72);
            #pragma unroll
            for (int i = 0; i < 2; i++) {
                wmma::mma_sync(acc[i][j], a_hi[i], b_hi, acc[i][j]);
                wmma::mma_sync(acc[i][j], a_hi[i], b_lo, acc[i][j]);
                wmma::mma_sync(acc[i][j], a_lo[i], b_hi, acc[i][j]);
            }
        }
    }

    __syncthreads();   // done reading Q/K smem; reuse as stage
    #pragma unroll
    for (int i = 0; i < 2; i++)
        #pragma unroll
        for (int j = 0; j < 4; j++)
            wmma::store_matrix_sync(&stage[(m_base + i*16)*132 + n_base + j*16],
                                    acc[i][j], 132, wmma::mem_row_major);
    __syncthreads();

    float* ap = attn + (size_t)h * S * S;
    const int tr = (tid >> 4) * 8;
    const int tc = (tid & 15) * 8;
    #pragma unroll
    for (int i = 0; i < 8; i++) {
        const size_t r = (size_t)(i0 + tr + i);
        uint4 m0v = *(const uint4*)(mask + r * S + j0 + tc);
        uint4 m1v = *(const uint4*)(mask + r * S + j0 + tc + 4);
        float4 s0 = *(const float4*)&stage[(tr + i)*132 + tc];
        float4 s1 = *(const float4*)&stage[(tr + i)*132 + tc + 4];
        float4 o0, o1;
        o0.x = m0v.x ? s0.x : -1e9f;
        o0.y = m0v.y ? s0.y : -1e9f;
        o0.z = m0v.z ? s0.z : -1e9f;
        o0.w = m0v.w ? s0.w : -1e9f;
        o1.x = m1v.x ? s1.x : -1e9f;
        o1.y = m1v.y ? s1.y : -1e9f;
        o1.z = m1v.z ? s1.z : -1e9f;
        o1.w = m1v.w ? s1.w : -1e9f;
        *(float4*)&ap[r * S + j0 + tc]     = o0;
        *(float4*)&ap[r * S + j0 + tc + 4] = o1;
    }
}

// ---------------------------------------------------------------------------
// Row softmax in place, vectorized. One block (256 threads) per row of S=2048.
// ---------------------------------------------------------------------------
__device__ __forceinline__ float warp_max(float v) {
    #pragma unroll
    for (int o = 16; o > 0; o >>= 1) v = fmaxf(v, __shfl_xor_sync(0xffffffffu, v, o));
    return v;
}
__device__ __forceinline__ float warp_sum(float v) {
    #pragma unroll
    for (int o = 16; o > 0; o >>= 1) v += __shfl_xor_sync(0xffffffffu, v, o);
    return v;
}

__global__ __launch_bounds__(256)
void softmax_k(float* __restrict__ attn)
{
    const size_t row = blockIdx.x;
    float4* p = (float4*)(attn + row * (size_t)S);
    const int t = threadIdx.x;
    const int warp = t >> 5, lane = t & 31;
    __shared__ float red[8];

    float4 v0 = p[t];
    float4 v1 = p[t + 256];

    float m = fmaxf(fmaxf(fmaxf(v0.x, v0.y), fmaxf(v0.z, v0.w)),
                    fmaxf(fmaxf(v1.x, v1.y), fmaxf(v1.z, v1.w)));
    m = warp_max(m);
    if (lane == 0) red[warp] = m;
    __syncthreads();
    m = red[lane & 7];
    m = warp_max(m);

    v0.x = expf(v0.x - m); v0.y = expf(v0.y - m);
    v0.z = expf(v0.z - m); v0.w = expf(v0.w - m);
    v1.x = expf(v1.x - m); v1.y = expf(v1.y - m);
    v1.z = expf(v1.z - m); v1.w = expf(v1.w - m);

    float s = v0.x + v0.y + v0.z + v0.w + v1.x + v1.y + v1.z + v1.w;
    s = warp_sum(s);
    __syncthreads();
    if (lane == 0) red[warp] = s;
    __syncthreads();
    s = (lane < 8) ? red[lane] : 0.0f;
    s = warp_sum(s);
    const float inv = 1.0f / s;

    v0.x *= inv; v0.y *= inv; v0.z *= inv; v0.w *= inv;
    v1.x *= inv; v1.y *= inv; v1.z *= inv; v1.w *= inv;
    p[t] = v0;
    p[t + 256] = v1;
}

// ---------------------------------------------------------------------------
// PV: outh[i, h*64+d] = sum_j attn[h,i,j] * Vg[j,d]
// 128x64 tile, BK=32, warp tile 32x32 (4x2 warps).
// ---------------------------------------------------------------------------
__global__ __launch_bounds__(256)
void pv_k(const float* __restrict__ attn,
          const float* __restrict__ vh,
          float* __restrict__ outh)
{
    __shared__ __align__(16) __nv_bfloat16 As_hi[128][40];
    __shared__ __align__(16) __nv_bfloat16 As_lo[128][40];
    __shared__ __align__(16) __nv_bfloat16 Bs_hi[32][72];
    __shared__ __align__(16) __nv_bfloat16 Bs_lo[32][72];

    const int tid  = threadIdx.x;
    const int warp = tid >> 5;
    const int i0 = blockIdx.x * 128;
    const int h  = blockIdx.y;
    const int g  = h >> 2;
    const int wm = warp >> 1;
    const int wn = warp & 1;
    const int m_base = wm * 32;
    const int n_base = wn * 32;

    const int la_m  = tid >> 1;           // 0..127
    const int la_k4 = (tid & 1) * 16;     // 0/16
    const int lb_k  = tid >> 3;           // 0..31
    const int lb_n  = (tid & 7) * 8;      // 0..56

    const float* Ap = attn + (size_t)h * S * S + (size_t)(i0 + la_m) * S + la_k4;
    const float* Bp = vh + (size_t)lb_k * GD + g * DK + lb_n;

    FragC acc[2][2];
    #pragma unroll
    for (int i = 0; i < 2; i++)
        #pragma unroll
        for (int j = 0; j < 2; j++)
            wmma::fill_fragment(acc[i][j], 0.0f);

    float4 pa[4], pb[2];
    #pragma unroll
    for (int q = 0; q < 4; q++) pa[q] = *(const float4*)(Ap + 4*q);
    #pragma unroll
    for (int q = 0; q < 2; q++) pb[q] = *(const float4*)(Bp + 4*q);

    for (int k0 = 0; k0 < S; k0 += 32) {
        #pragma unroll
        for (int q = 0; q < 4; q++)
            store_split4(pa[q], &As_hi[la_m][la_k4 + 4*q], &As_lo[la_m][la_k4 + 4*q]);
        #pragma unroll
        for (int q = 0; q < 2; q++)
            store_split4(pb[q], &Bs_hi[lb_k][lb_n + 4*q], &Bs_lo[lb_k][lb_n + 4*q]);
        __syncthreads();

        if (k0 + 32 < S) {
            #pragma unroll
            for (int q = 0; q < 4; q++) pa[q] = *(const float4*)(Ap + k0 + 32 + 4*q);
            #pragma unroll
            for (int q = 0; q < 2; q++) pb[q] = *(const float4*)(Bp + (size_t)(k0 + 32) * GD + 4*q);
        }

        #pragma unroll
        for (int kf = 0; kf < 2; kf++) {
            FragA a_hi[2], a_lo[2];
            #pragma unroll
            for (int i = 0; i < 2; i++) {
                wmma::load_matrix_sync(a_hi[i], &As_hi[m_base + i*16][kf*16], 40);
                wmma::load_matrix_sync(a_lo[i], &As_lo[m_base + i*16][kf*16], 40);
            }
            #pragma unroll
            for (int j = 0; j < 2; j++) {
                FragBr b_hi, b_lo;
                wmma::load_matrix_sync(b_hi, &Bs_hi[kf*16][n_base + j*16], 72);
                wmma::load_matrix_sync(b_lo, &Bs_lo[kf*16][n_base + j*16], 72);
                #pragma unroll
                for (int i = 0; i < 2; i++) {
                    wmma::mma_sync(acc[i][j], a_hi[i], b_hi, acc[i][j]);
                    wmma::mma_sync(acc[i][j], a_hi[i], b_lo, acc[i][j]);
                    wmma::mma_sync(acc[i][j], a_lo[i], b_hi, acc[i][j]);
                }
            }
        }
        __syncthreads();
    }

    #pragma unroll
    for (int i = 0; i < 2; i++)
        #pragma unroll
        for (int j = 0; j < 2; j++)
            wmma::store_matrix_sync(outh + (size_t)(i0 + m_base + i*16) * HD + h * DK + n_base + j*16,
                                    acc[i][j], HD, wmma::mem_row_major);
}

// ---------------------------------------------------------------------------
extern "C" void kernel_launch(void* const* d_in, const int* in_sizes, int n_in,
                              void* d_out, int out_size)
{
    const float*        q    = (const float*)d_in[0];
    const float*        k    = (const float*)d_in[1];
    const float*        v    = (const float*)d_in[2];
    const unsigned int* mask = (const unsigned int*)d_in[3];
    const float*        wq   = (const float*)d_in[4];
    const float*        bq   = (const float*)d_in[5];
    const float*        wk   = (const float*)d_in[6];
    const float*        bk   = (const float*)d_in[7];
    const float*        wv   = (const float*)d_in[8];
    const float*        bv   = (const float*)d_in[9];
    const float*        wo   = (const float*)d_in[10];
    const float*        bo   = (const float*)d_in[11];

    float* out  = (float*)d_out;
    float* attn = out + (size_t)S * DM;   // outputs: [out | attn]

    float *qh, *kh, *vh, *outh;
    cudaGetSymbolAddress((void**)&qh,   g_qh);
    cudaGetSymbolAddress((void**)&kh,   g_kh);
    cudaGetSymbolAddress((void**)&vh,   g_vh);
    cudaGetSymbolAddress((void**)&outh, g_outh);

    const int scores_smem = 4 * 128 * 72 * (int)sizeof(__nv_bfloat16);  // 73728
    cudaFuncSetAttribute(scores_k, cudaFuncAttributeMaxDynamicSharedMemorySize, scores_smem);

    // Projections
    gemm_bias_k<<<dim3(HD / 128, S / 128), 256>>>(q, wq, bq, qh, S, HD, DM);
    gemm_bias_k<<<dim3(GD / 128, S / 128), 256>>>(k, wk, bk, kh, S, GD, DM);
    gemm_bias_k<<<dim3(GD / 128, S / 128), 256>>>(v, wv, bv, vh, S, GD, DM);

    // Scores (scaled + masked) into attn output region
    scores_k<<<dim3(S / 128, S / 128, H), 256, scores_smem>>>(qh, kh, mask, attn);

    // Row softmax in place
    softmax_k<<<H * S, 256>>>(attn);

    // attn @ V
    pv_k<<<dim3(S / 128, H), 256>>>(attn, vh, outh);

    // Output projection
    gemm_bias_k<<<dim3(DM / 128, S / 128), 256>>>(outh, wo, bo, out, S, DM, HD);
}